// round 10
// baseline (speedup 1.0000x reference)
#include <cuda_runtime.h>
#include <math.h>
#include <stdint.h>

#define UNITS 1024
#define FEAT  1024
#define GCOLS 4096                  // 4 * UNITS gate columns
#define CTILE 128                   // columns per block (32 lanes x float4)
#define NCB   (GCOLS / CTILE)       // 32 column tiles
#define KS    4                     // k-slices
#define KROWS (FEAT / KS)           // 256 k-rows per block
#define WARPS 32                    // warps per block (1024 threads)
#define KPW   (KROWS / WARPS)       // 8 k-rows per warp

#define TILE_BYTES (KROWS * CTILE * 4)      // 131072 B per block tile
#define ROW_BYTES  (CTILE * 4)              // 512 B per k-row

// dynamic smem layout:  [mbar 16B][Wt tile][xs0][xs1][sred0][sred1]
#define OFF_MBAR  0
#define OFF_TILE  16
#define OFF_XS0   (OFF_TILE + TILE_BYTES)
#define OFF_XS1   (OFF_XS0 + KROWS * 4)
#define OFF_SRED0 (OFF_XS1 + KROWS * 4)
#define OFF_SRED1 (OFF_SRED0 + WARPS * 32 * 16)
#define SMEM_XW   (OFF_SRED1 + WARPS * 32 * 16)          // ~166KB
// k_hu: [mbar 16B][Ut tile][h0s][sred]
#define OFF_H0S   (OFF_TILE + TILE_BYTES)
#define OFF_SREDU (OFF_H0S + KROWS * 4)
#define SMEM_HU   (OFF_SREDU + WARPS * 32 * 16)          // ~149KB

// Scratch (device globals)
__device__ float4 g_p0[KS][GCOLS / 4];   // partials of x0@W (per k-slice)
__device__ float4 g_p1[KS][GCOLS / 4];   // partials of x1@W
__device__ float4 g_pu[KS][GCOLS / 4];   // partials of h0@U

__device__ __forceinline__ float sigmoidf_(float x) {
    return 1.0f / (1.0f + expf(-x));
}

__device__ __forceinline__ unsigned smem_u32(const void* p) {
    return (unsigned)__cvta_generic_to_shared(p);
}
__device__ __forceinline__ void mbar_init(unsigned mbar, unsigned count) {
    asm volatile("mbarrier.init.shared.b64 [%0], %1;" :: "r"(mbar), "r"(count) : "memory");
}
__device__ __forceinline__ void mbar_expect_tx(unsigned mbar, unsigned bytes) {
    asm volatile("mbarrier.arrive.expect_tx.shared.b64 _, [%0], %1;"
                 :: "r"(mbar), "r"(bytes) : "memory");
}
__device__ __forceinline__ void mbar_wait(unsigned mbar, unsigned parity) {
    asm volatile(
        "{\n\t"
        ".reg .pred P1;\n\t"
        "WAIT_LOOP_%=:\n\t"
        "mbarrier.try_wait.parity.acquire.cta.shared::cta.b64 P1, [%0], %1, 0x989680;\n\t"
        "@P1 bra.uni WAIT_DONE_%=;\n\t"
        "bra.uni WAIT_LOOP_%=;\n\t"
        "WAIT_DONE_%=:\n\t"
        "}"
        :: "r"(mbar), "r"(parity) : "memory");
}
// 1D bulk async copy global->shared (TMA path, SASS UBLKCP.S.G)
__device__ __forceinline__ void bulk_g2s(unsigned sdst, const void* gsrc,
                                         unsigned bytes, unsigned mbar) {
    asm volatile(
        "cp.async.bulk.shared::cluster.global.mbarrier::complete_tx::bytes "
        "[%0], [%1], %2, [%3];"
        :: "r"(sdst), "l"(gsrc), "r"(bytes), "r"(mbar) : "memory");
}

// Fold the KS partials of a gate column (fixed order) — scalar view.
__device__ __forceinline__ float fold_p(const float4 (*p)[GCOLS / 4], int col) {
    const float* base = reinterpret_cast<const float*>(p);
    float s = 0.f;
    #pragma unroll
    for (int sI = 0; sI < KS; ++sI) s += base[sI * GCOLS + col];
    return s;
}

// ---------------------------------------------------------------------------
// Kernel 1: partial GEMV over W for timesteps 0 and 1.
// grid = (NCB, KS) = (32, 4) = 128 blocks x 1024 threads.
// Block (cb, ks): columns [cb*128, cb*128+128), k in [ks*256, ks*256+256).
// The 128KB W tile is pulled into shared by 256 TMA 1D bulk copies (512B/row)
// completing on one mbarrier; compute consumes from shared.
// ---------------------------------------------------------------------------
__global__ void __launch_bounds__(1024, 1)
k_xw(const float* __restrict__ x, const float* __restrict__ W) {
    extern __shared__ char dyn[];
    float* Wt  = (float*)(dyn + OFF_TILE);
    float* xs0 = (float*)(dyn + OFF_XS0);
    float* xs1 = (float*)(dyn + OFF_XS1);
    float4* sred0 = (float4*)(dyn + OFF_SRED0);
    float4* sred1 = (float4*)(dyn + OFF_SRED1);
    const unsigned mbar = smem_u32(dyn + OFF_MBAR);

    const int tid  = threadIdx.x;
    const int lane = tid & 31;
    const int r    = tid >> 5;
    const int cb   = blockIdx.x;
    const int ks   = blockIdx.y;
    const int kbase = ks * KROWS;

    if (tid == 0) {
        mbar_init(mbar, 1);
        mbar_expect_tx(mbar, TILE_BYTES);
    }
    __syncthreads();

    // 256 bulk copies, one 512B k-row each (TMA engine, deep pipelining)
    const char* gW = (const char*)(W + (size_t)kbase * GCOLS + cb * CTILE);
    if (tid < KROWS) {
        bulk_g2s(smem_u32(Wt + tid * CTILE), gW + (size_t)tid * (GCOLS * 4),
                 ROW_BYTES, mbar);
    }
    // x slices via regular loads while the tile streams
    for (int i = tid; i < KROWS; i += 1024) {
        xs0[i] = x[kbase + i];
        xs1[i] = x[FEAT + kbase + i];
    }
    __syncthreads();
    mbar_wait(mbar, 0);

    // consume from shared: warp r -> k-rows r*8..r*8+7, lane -> float4 col
    float4 a0 = make_float4(0.f, 0.f, 0.f, 0.f);
    float4 a1 = make_float4(0.f, 0.f, 0.f, 0.f);
    #pragma unroll
    for (int kk = 0; kk < KPW; ++kk) {
        const int row = r * KPW + kk;
        const float4 w = reinterpret_cast<const float4*>(Wt + row * CTILE)[lane];
        const float xa = xs0[row];
        const float xb = xs1[row];
        a0.x = fmaf(xa, w.x, a0.x); a0.y = fmaf(xa, w.y, a0.y);
        a0.z = fmaf(xa, w.z, a0.z); a0.w = fmaf(xa, w.w, a0.w);
        a1.x = fmaf(xb, w.x, a1.x); a1.y = fmaf(xb, w.y, a1.y);
        a1.z = fmaf(xb, w.z, a1.z); a1.w = fmaf(xb, w.w, a1.w);
    }
    sred0[r * 32 + lane] = a0;
    sred1[r * 32 + lane] = a1;
    __syncthreads();

    if (tid < 32) {
        float4 s0 = make_float4(0.f, 0.f, 0.f, 0.f);
        #pragma unroll
        for (int rr = 0; rr < WARPS; ++rr) {
            const float4 v = sred0[rr * 32 + tid];
            s0.x += v.x; s0.y += v.y; s0.z += v.z; s0.w += v.w;
        }
        g_p0[ks][cb * 32 + tid] = s0;
    } else if (tid < 64) {
        const int c = tid - 32;
        float4 s1 = make_float4(0.f, 0.f, 0.f, 0.f);
        #pragma unroll
        for (int rr = 0; rr < WARPS; ++rr) {
            const float4 v = sred1[rr * 32 + c];
            s1.x += v.x; s1.y += v.y; s1.z += v.z; s1.w += v.w;
        }
        g_p1[ks][cb * 32 + c] = s1;
    }
}

// ---------------------------------------------------------------------------
// Kernel 2: partial GEMV over U (same TMA staging). Each block reconstructs
// the 256 h0 values it needs from the x@W partials (+b) while the tile loads.
// ---------------------------------------------------------------------------
__global__ void __launch_bounds__(1024, 1)
k_hu(const float* __restrict__ U, const float* __restrict__ b) {
    extern __shared__ char dyn[];
    float* Ut  = (float*)(dyn + OFF_TILE);
    float* h0s = (float*)(dyn + OFF_H0S);
    float4* sred = (float4*)(dyn + OFF_SREDU);
    const unsigned mbar = smem_u32(dyn + OFF_MBAR);

    const int tid  = threadIdx.x;
    const int lane = tid & 31;
    const int r    = tid >> 5;
    const int cb   = blockIdx.x;
    const int ks   = blockIdx.y;
    const int kbase = ks * KROWS;

    if (tid == 0) {
        mbar_init(mbar, 1);
        mbar_expect_tx(mbar, TILE_BYTES);
    }
    __syncthreads();

    const char* gU = (const char*)(U + (size_t)kbase * GCOLS + cb * CTILE);
    if (tid < KROWS) {
        bulk_g2s(smem_u32(Ut + tid * CTILE), gU + (size_t)tid * (GCOLS * 4),
                 ROW_BYTES, mbar);
    }
    // reconstruct h0 slice while the tile streams in (c_prev = 0)
    if (tid < KROWS) {
        const int u = kbase + tid;
        const float zi = fold_p(g_p0, u)             + __ldg(b + u);
        const float zg = fold_p(g_p0, 2 * UNITS + u) + __ldg(b + 2 * UNITS + u);
        const float zo = fold_p(g_p0, 3 * UNITS + u) + __ldg(b + 3 * UNITS + u);
        const float c0 = sigmoidf_(zi) * zg;
        h0s[tid] = sigmoidf_(zo) * c0;
    }
    __syncthreads();
    mbar_wait(mbar, 0);

    float4 a = make_float4(0.f, 0.f, 0.f, 0.f);
    #pragma unroll
    for (int kk = 0; kk < KPW; ++kk) {
        const int row = r * KPW + kk;
        const float4 w = reinterpret_cast<const float4*>(Ut + row * CTILE)[lane];
        const float h = h0s[row];
        a.x = fmaf(h, w.x, a.x); a.y = fmaf(h, w.y, a.y);
        a.z = fmaf(h, w.z, a.z); a.w = fmaf(h, w.w, a.w);
    }
    sred[r * 32 + lane] = a;
    __syncthreads();

    if (tid < 32) {
        float4 s = make_float4(0.f, 0.f, 0.f, 0.f);
        #pragma unroll
        for (int rr = 0; rr < WARPS; ++rr) {
            const float4 v = sred[rr * 32 + tid];
            s.x += v.x; s.y += v.y; s.z += v.z; s.w += v.w;
        }
        g_pu[ks][cb * 32 + tid] = s;
    }
}

// ---------------------------------------------------------------------------
// Kernel 3: one block, 1024 threads = UNITS. Fold all partials, gate math for
// t=0 and t=1, dense head via deterministic in-block reduction, finite diff.
// ---------------------------------------------------------------------------
__global__ void k_final(const float* __restrict__ f,
                        const float* __restrict__ b,
                        const float* __restrict__ Wd,
                        const float* __restrict__ bd,
                        float* __restrict__ out) {
    __shared__ float red[4][32];
    const int u = threadIdx.x;   // 0..1023

    const float zi0 = fold_p(g_p0, u)             + __ldg(b + u);
    const float zg0 = fold_p(g_p0, 2 * UNITS + u) + __ldg(b + 2 * UNITS + u);
    const float zo0 = fold_p(g_p0, 3 * UNITS + u) + __ldg(b + 3 * UNITS + u);
    const float c0  = sigmoidf_(zi0) * zg0;
    const float h0  = sigmoidf_(zo0) * c0;

    const float zi1 = fold_p(g_p1, u)             + fold_p(g_pu, u)             + __ldg(b + u);
    const float zf1 = fold_p(g_p1, UNITS + u)     + fold_p(g_pu, UNITS + u)     + __ldg(b + UNITS + u);
    const float zg1 = fold_p(g_p1, 2 * UNITS + u) + fold_p(g_pu, 2 * UNITS + u) + __ldg(b + 2 * UNITS + u);
    const float zo1 = fold_p(g_p1, 3 * UNITS + u) + fold_p(g_pu, 3 * UNITS + u) + __ldg(b + 3 * UNITS + u);
    const float c1  = sigmoidf_(zf1) * c0 + sigmoidf_(zi1) * zg1;
    const float h1  = sigmoidf_(zo1) * c1;

    const float n0 = tanhf(h0);
    const float n1 = tanhf(h1);

    const float wd0 = __ldg(Wd + 2 * u);
    const float wd1 = __ldg(Wd + 2 * u + 1);
    float v0 = n0 * wd0;   // -> h_c[0,0]
    float v1 = n0 * wd1;   // -> h_c[0,1]
    float v2 = n1 * wd0;   // -> h_c[1,0]
    float v3 = n1 * wd1;   // -> h_c[1,1]

    const unsigned m = 0xffffffffu;
    const int lane = u & 31;
    const int wrp  = u >> 5;
    #pragma unroll
    for (int off = 16; off > 0; off >>= 1) {
        v0 += __shfl_down_sync(m, v0, off);
        v1 += __shfl_down_sync(m, v1, off);
        v2 += __shfl_down_sync(m, v2, off);
        v3 += __shfl_down_sync(m, v3, off);
    }
    if (lane == 0) {
        red[0][wrp] = v0; red[1][wrp] = v1; red[2][wrp] = v2; red[3][wrp] = v3;
    }
    __syncthreads();

    if (wrp == 0) {
        float r0 = red[0][lane];
        float r1 = red[1][lane];
        float r2 = red[2][lane];
        float r3 = red[3][lane];
        #pragma unroll
        for (int off = 16; off > 0; off >>= 1) {
            r0 += __shfl_down_sync(m, r0, off);
            r1 += __shfl_down_sync(m, r1, off);
            r2 += __shfl_down_sync(m, r2, off);
            r3 += __shfl_down_sync(m, r3, off);
        }
        if (lane == 0) {
            const float b0 = __ldg(bd + 0);
            const float b1 = __ldg(bd + 1);
            const float hc00 = tanhf(r0 + b0);   // h_c[0,0]
            const float hc01 = tanhf(r1 + b1);   // h_c[0,1]
            const float hc10 = tanhf(r2 + b0);   // h_c[1,0]
            const float hc11 = tanhf(r3 + b1);   // h_c[1,1]
            const float den  = __ldg(f + 1) - __ldg(f + 2);
            out[0] = hc00;                       // h_out
            out[1] = hc01;
            out[2] = (hc00 - hc10) / den;        // H
            out[3] = (hc01 - hc11) / den;
        }
    }
}

// ---------------------------------------------------------------------------
extern "C" void kernel_launch(void* const* d_in, const int* in_sizes, int n_in,
                              void* d_out, int out_size) {
    (void)in_sizes; (void)n_in; (void)out_size;
    const float* x  = (const float*)d_in[0];   // inputs (1, 8192, 1024)
    const float* f  = (const float*)d_in[1];   // f (8192, 1)
    const float* W  = (const float*)d_in[2];   // (1024, 4096)
    const float* U  = (const float*)d_in[3];   // (1024, 4096)
    const float* b  = (const float*)d_in[4];   // (4096,)
    const float* Wd = (const float*)d_in[5];   // (1024, 2)
    const float* bd = (const float*)d_in[6];   // (2,)
    float* out = (float*)d_out;

    cudaFuncSetAttribute(k_xw, cudaFuncAttributeMaxDynamicSharedMemorySize, SMEM_XW);
    cudaFuncSetAttribute(k_hu, cudaFuncAttributeMaxDynamicSharedMemorySize, SMEM_HU);

    dim3 grid(NCB, KS);   // (32, 4) = 128 blocks
    k_xw   <<<grid, 1024, SMEM_XW>>>(x, W);
    k_hu   <<<grid, 1024, SMEM_HU>>>(U, b);
    k_final<<<1, 1024>>>(f, b, Wd, bd, out);
}

// round 11
// speedup vs baseline: 1.0172x; 1.0172x over previous
#include <cuda_runtime.h>
#include <math.h>

#define UNITS 1024
#define FEAT  1024
#define GCOLS 4096                  // 4 * UNITS gate columns
#define CTILE 128                   // columns per block (32 lanes x float4)
#define NCB   (GCOLS / CTILE)       // 32 column tiles
#define KS    4                     // k-slices
#define NBLK  (NCB * KS)            // 128 blocks
#define KROWS (FEAT / KS)           // 256 k-rows per block
#define WARPS 32                    // warps per block (1024 threads)
#define KPW   (KROWS / WARPS)       // 8 k-rows per warp

// Scratch (device globals)
__device__ float4 g_p0[KS][GCOLS / 4];   // partials of x0@W (per k-slice)
__device__ float4 g_p1[KS][GCOLS / 4];   // partials of x1@W
__device__ float4 g_pu[KS][GCOLS / 4];   // partials of h0@U
__device__ int    g_cnt;                 // last-block counter (zero-init)

__device__ __forceinline__ float sigmoidf_(float x) {
    return 1.0f / (1.0f + expf(-x));
}

// Fold the KS partials of a gate column (fixed order) — scalar view.
__device__ __forceinline__ float fold_p(const float4 (*p)[GCOLS / 4], int col) {
    const float* base = reinterpret_cast<const float*>(p);
    float s = 0.f;
    #pragma unroll
    for (int sI = 0; sI < KS; ++sI) s += base[sI * GCOLS + col];
    return s;
}

// ---------------------------------------------------------------------------
// Kernel 1: partial GEMV over W for timesteps 0 and 1.  (R7 structure)
// grid = (NCB, KS) = (32, 4) = 128 blocks x 1024 threads.
// Block (cb, ks): columns [cb*128, cb*128+128), k in [ks*256, ks*256+256).
// Lane loads float4 of 4 consecutive columns; warp r covers k-rows r*8..r*8+7.
// ---------------------------------------------------------------------------
__global__ void __launch_bounds__(1024, 1)
k_xw(const float* __restrict__ x, const float* __restrict__ W) {
    __shared__ float  xs0[KROWS], xs1[KROWS];
    __shared__ float4 sred0[WARPS][32];
    __shared__ float4 sred1[WARPS][32];
    const int tid  = threadIdx.x;
    const int lane = tid & 31;
    const int r    = tid >> 5;
    const int cb   = blockIdx.x;
    const int ks   = blockIdx.y;
    const int colv = cb * 32 + lane;          // float4-column index (0..1023)
    const int kbase = ks * KROWS;

    for (int i = tid; i < KROWS; i += 1024) {
        xs0[i] = x[kbase + i];
        xs1[i] = x[FEAT + kbase + i];
    }
    __syncthreads();

    const float4* Wp = reinterpret_cast<const float4*>(W)
                     + (size_t)(kbase + r * KPW) * (GCOLS / 4) + colv;
    float4 a0 = make_float4(0.f, 0.f, 0.f, 0.f);
    float4 a1 = make_float4(0.f, 0.f, 0.f, 0.f);
    #pragma unroll
    for (int kk = 0; kk < KPW; ++kk) {
        const float4 w = Wp[(size_t)kk * (GCOLS / 4)];
        const float xa = xs0[r * KPW + kk];
        const float xb = xs1[r * KPW + kk];
        a0.x = fmaf(xa, w.x, a0.x); a0.y = fmaf(xa, w.y, a0.y);
        a0.z = fmaf(xa, w.z, a0.z); a0.w = fmaf(xa, w.w, a0.w);
        a1.x = fmaf(xb, w.x, a1.x); a1.y = fmaf(xb, w.y, a1.y);
        a1.z = fmaf(xb, w.z, a1.z); a1.w = fmaf(xb, w.w, a1.w);
    }
    sred0[r][lane] = a0;
    sred1[r][lane] = a1;
    __syncthreads();

    if (tid < 32) {
        float4 s0 = make_float4(0.f, 0.f, 0.f, 0.f);
        #pragma unroll
        for (int rr = 0; rr < WARPS; ++rr) {
            const float4 v = sred0[rr][tid];
            s0.x += v.x; s0.y += v.y; s0.z += v.z; s0.w += v.w;
        }
        g_p0[ks][cb * 32 + tid] = s0;
    } else if (tid < 64) {
        const int c = tid - 32;
        float4 s1 = make_float4(0.f, 0.f, 0.f, 0.f);
        #pragma unroll
        for (int rr = 0; rr < WARPS; ++rr) {
            const float4 v = sred1[rr][c];
            s1.x += v.x; s1.y += v.y; s1.z += v.z; s1.w += v.w;
        }
        g_p1[ks][cb * 32 + c] = s1;
    }
}

// ---------------------------------------------------------------------------
// Kernel 2: partial GEMV over U + fused finale.
// Same geometry as k_xw. U tile is prefetched into registers FIRST (no
// dependency), then each block reconstructs the 256 h0 values it needs from
// the x@W partials (+b) while the loads are in flight. After writing its
// g_pu slice, the last-arriving block folds everything, does gate math for
// t=0/t=1, the dense head, finite diff, and writes the 4 outputs.
// ---------------------------------------------------------------------------
__global__ void __launch_bounds__(1024, 1)
k_hu(const float* __restrict__ U, const float* __restrict__ b,
     const float* __restrict__ f, const float* __restrict__ Wd,
     const float* __restrict__ bd, float* __restrict__ out) {
    __shared__ float  h0s[KROWS];
    __shared__ float4 sred[WARPS][32];
    __shared__ float  red[4][32];
    __shared__ int    is_last;

    const int tid  = threadIdx.x;
    const int lane = tid & 31;
    const int r    = tid >> 5;
    const int cb   = blockIdx.x;
    const int ks   = blockIdx.y;
    const int colv = cb * 32 + lane;
    const int kbase = ks * KROWS;

    // Prefetch U tile into registers (independent of everything below).
    const float4* Up = reinterpret_cast<const float4*>(U)
                     + (size_t)(kbase + r * KPW) * (GCOLS / 4) + colv;
    float4 w[KPW];
    #pragma unroll
    for (int kk = 0; kk < KPW; ++kk) {
        w[kk] = Up[(size_t)kk * (GCOLS / 4)];
    }

    // Reconstruct h0 slice while the prefetch is in flight (c_prev = 0).
    if (tid < KROWS) {
        const int u = kbase + tid;
        const float zi = fold_p(g_p0, u)             + __ldg(b + u);
        const float zg = fold_p(g_p0, 2 * UNITS + u) + __ldg(b + 2 * UNITS + u);
        const float zo = fold_p(g_p0, 3 * UNITS + u) + __ldg(b + 3 * UNITS + u);
        const float c0 = sigmoidf_(zi) * zg;
        h0s[tid] = sigmoidf_(zo) * c0;
    }
    __syncthreads();

    float4 a = make_float4(0.f, 0.f, 0.f, 0.f);
    #pragma unroll
    for (int kk = 0; kk < KPW; ++kk) {
        const float h = h0s[r * KPW + kk];
        a.x = fmaf(h, w[kk].x, a.x); a.y = fmaf(h, w[kk].y, a.y);
        a.z = fmaf(h, w[kk].z, a.z); a.w = fmaf(h, w[kk].w, a.w);
    }
    sred[r][lane] = a;
    __syncthreads();

    if (tid < 32) {
        float4 s = make_float4(0.f, 0.f, 0.f, 0.f);
        #pragma unroll
        for (int rr = 0; rr < WARPS; ++rr) {
            const float4 v = sred[rr][tid];
            s.x += v.x; s.y += v.y; s.z += v.z; s.w += v.w;
        }
        g_pu[ks][cb * 32 + tid] = s;
    }
    __syncthreads();

    if (tid == 0) {
        __threadfence();                       // release our g_pu writes
        const int arrived = atomicAdd(&g_cnt, 1);
        is_last = (arrived == NBLK - 1) ? 1 : 0;
        if (is_last) __threadfence();          // acquire everyone's writes
    }
    __syncthreads();
    if (!is_last) return;

    // ---- finale (one block, 1024 threads = UNITS) ----
    const int u = tid;

    const float zi0 = fold_p(g_p0, u)             + __ldg(b + u);
    const float zg0 = fold_p(g_p0, 2 * UNITS + u) + __ldg(b + 2 * UNITS + u);
    const float zo0 = fold_p(g_p0, 3 * UNITS + u) + __ldg(b + 3 * UNITS + u);
    const float c0  = sigmoidf_(zi0) * zg0;
    const float h0  = sigmoidf_(zo0) * c0;

    const float zi1 = fold_p(g_p1, u)             + fold_p(g_pu, u)             + __ldg(b + u);
    const float zf1 = fold_p(g_p1, UNITS + u)     + fold_p(g_pu, UNITS + u)     + __ldg(b + UNITS + u);
    const float zg1 = fold_p(g_p1, 2 * UNITS + u) + fold_p(g_pu, 2 * UNITS + u) + __ldg(b + 2 * UNITS + u);
    const float zo1 = fold_p(g_p1, 3 * UNITS + u) + fold_p(g_pu, 3 * UNITS + u) + __ldg(b + 3 * UNITS + u);
    const float c1  = sigmoidf_(zf1) * c0 + sigmoidf_(zi1) * zg1;
    const float h1  = sigmoidf_(zo1) * c1;

    const float n0 = tanhf(h0);
    const float n1 = tanhf(h1);

    const float wd0 = __ldg(Wd + 2 * u);
    const float wd1 = __ldg(Wd + 2 * u + 1);
    float v0 = n0 * wd0;   // -> h_c[0,0]
    float v1 = n0 * wd1;   // -> h_c[0,1]
    float v2 = n1 * wd0;   // -> h_c[1,0]
    float v3 = n1 * wd1;   // -> h_c[1,1]

    const unsigned m = 0xffffffffu;
    #pragma unroll
    for (int off = 16; off > 0; off >>= 1) {
        v0 += __shfl_down_sync(m, v0, off);
        v1 += __shfl_down_sync(m, v1, off);
        v2 += __shfl_down_sync(m, v2, off);
        v3 += __shfl_down_sync(m, v3, off);
    }
    if (lane == 0) {
        red[0][r] = v0; red[1][r] = v1; red[2][r] = v2; red[3][r] = v3;
    }
    __syncthreads();

    if (r == 0) {
        float r0 = red[0][lane];
        float r1 = red[1][lane];
        float r2 = red[2][lane];
        float r3 = red[3][lane];
        #pragma unroll
        for (int off = 16; off > 0; off >>= 1) {
            r0 += __shfl_down_sync(m, r0, off);
            r1 += __shfl_down_sync(m, r1, off);
            r2 += __shfl_down_sync(m, r2, off);
            r3 += __shfl_down_sync(m, r3, off);
        }
        if (lane == 0) {
            const float b0 = __ldg(bd + 0);
            const float b1 = __ldg(bd + 1);
            const float hc00 = tanhf(r0 + b0);   // h_c[0,0]
            const float hc01 = tanhf(r1 + b1);   // h_c[0,1]
            const float hc10 = tanhf(r2 + b0);   // h_c[1,0]
            const float hc11 = tanhf(r3 + b1);   // h_c[1,1]
            const float den  = __ldg(f + 1) - __ldg(f + 2);
            out[0] = hc00;                       // h_out
            out[1] = hc01;
            out[2] = (hc00 - hc10) / den;        // H
            out[3] = (hc01 - hc11) / den;
            g_cnt = 0;                           // reset for next replay
        }
    }
}

// ---------------------------------------------------------------------------
extern "C" void kernel_launch(void* const* d_in, const int* in_sizes, int n_in,
                              void* d_out, int out_size) {
    (void)in_sizes; (void)n_in; (void)out_size;
    const float* x  = (const float*)d_in[0];   // inputs (1, 8192, 1024)
    const float* f  = (const float*)d_in[1];   // f (8192, 1)
    const float* W  = (const float*)d_in[2];   // (1024, 4096)
    const float* U  = (const float*)d_in[3];   // (1024, 4096)
    const float* b  = (const float*)d_in[4];   // (4096,)
    const float* Wd = (const float*)d_in[5];   // (1024, 2)
    const float* bd = (const float*)d_in[6];   // (2,)
    float* out = (float*)d_out;

    dim3 grid(NCB, KS);   // (32, 4) = 128 blocks
    k_xw<<<grid, 1024>>>(x, W);
    k_hu<<<grid, 1024>>>(U, b, f, Wd, bd, out);
}